// round 7
// baseline (speedup 1.0000x reference)
#include <cuda_runtime.h>
#include <cuda_bf16.h>
#include <cstdint>
#include <cstddef>

#define TOKENS 16384
#define DIM    1024
#define INNER  4096
#define WELEMS 4194304  // 4096*1024

// ---------------- scratch (static device globals; no allocation) ----------------
__device__ __align__(1024) int8_t g_xq [(size_t)TOKENS * DIM];
__device__ __align__(1024) int8_t g_hq [(size_t)TOKENS * INNER];
__device__ __align__(1024) int8_t g_w1q[WELEMS];
__device__ __align__(1024) int8_t g_w2q[WELEMS];
__device__ __align__(1024) float  g_h  [(size_t)TOKENS * INNER];
__device__ float g_xdq[TOKENS];
__device__ float g_hdq[TOKENS];
__device__ float g_part[1024];
__device__ float g_wdq[2];   // dequant = clip(mean|w|,eps)
__device__ float g_wqs[2];   // 1/dequant

// ---------------- helpers ----------------
__device__ __forceinline__ uint32_t smem_u32(const void* p) {
    return (uint32_t)__cvta_generic_to_shared(p);
}
// SW128 swizzle on byte offsets (128B rows)
__device__ __forceinline__ uint32_t swz(uint32_t x) { return x ^ ((x >> 3) & 0x70); }

__device__ __forceinline__ void cp16(uint32_t s, const void* g) {
    asm volatile("cp.async.cg.shared.global [%0], [%1], 16;" :: "r"(s), "l"(g) : "memory");
}
__device__ __forceinline__ void ldsm4(uint32_t* r, uint32_t a) {
    asm volatile("ldmatrix.sync.aligned.m8n8.x4.shared.b16 {%0,%1,%2,%3}, [%4];"
                 : "=r"(r[0]), "=r"(r[1]), "=r"(r[2]), "=r"(r[3]) : "r"(a));
}
// int8 IMMA: D(s32) += A(s8,16x32) * B(s8,32x8). Fragment layout is byte-identical
// to the bf16 m16n8k16 layout, so ldmatrix.b16 addressing carries over.
__device__ __forceinline__ void mma_s8(int* c, const uint32_t* a, uint32_t b0, uint32_t b1) {
    asm volatile(
        "mma.sync.aligned.m16n8k32.row.col.s32.s8.s8.s32 "
        "{%0,%1,%2,%3}, {%4,%5,%6,%7}, {%8,%9}, {%0,%1,%2,%3};"
        : "+r"(c[0]), "+r"(c[1]), "+r"(c[2]), "+r"(c[3])
        : "r"(a[0]), "r"(a[1]), "r"(a[2]), "r"(a[3]), "r"(b0), "r"(b1));
}

__device__ __forceinline__ uint32_t pack4(float a0, float a1, float a2, float a3) {
    int i0 = __float2int_rn(a0), i1 = __float2int_rn(a1);
    int i2 = __float2int_rn(a2), i3 = __float2int_rn(a3);
    i0 = max(-128, min(127, i0)); i1 = max(-128, min(127, i1));
    i2 = max(-128, min(127, i2)); i3 = max(-128, min(127, i3));
    return (uint32_t)(i0 & 0xFF) | ((uint32_t)(i1 & 0xFF) << 8)
         | ((uint32_t)(i2 & 0xFF) << 16) | ((uint32_t)(i3 & 0xFF) << 24);
}

// ---------------- weight quantization ----------------
__global__ void __launch_bounds__(256) wabs_kernel(const float* __restrict__ w1,
                                                   const float* __restrict__ w2) {
    const float* w = blockIdx.y ? w2 : w1;
    float s = 0.f;
    for (int i = blockIdx.x * 256 + threadIdx.x; i < WELEMS; i += 512 * 256)
        s += fabsf(w[i]);
    #pragma unroll
    for (int o = 16; o; o >>= 1) s += __shfl_xor_sync(~0u, s, o);
    __shared__ float sm[8];
    if ((threadIdx.x & 31) == 0) sm[threadIdx.x >> 5] = s;
    __syncthreads();
    if (threadIdx.x == 0) {
        float t = 0.f;
        #pragma unroll
        for (int i = 0; i < 8; i++) t += sm[i];
        g_part[blockIdx.y * 512 + blockIdx.x] = t;
    }
}

__global__ void __launch_bounds__(512) wfin_kernel() {
    int t = threadIdx.x;
    float a = g_part[t], b = g_part[512 + t];
    #pragma unroll
    for (int o = 16; o; o >>= 1) {
        a += __shfl_xor_sync(~0u, a, o);
        b += __shfl_xor_sync(~0u, b, o);
    }
    __shared__ float sa[16], sb[16];
    if ((t & 31) == 0) { sa[t >> 5] = a; sb[t >> 5] = b; }
    __syncthreads();
    if (t == 0) {
        float ta = 0.f, tb = 0.f;
        #pragma unroll
        for (int i = 0; i < 16; i++) { ta += sa[i]; tb += sb[i]; }
        float m1 = fmaxf(ta * (1.0f / WELEMS), 1e-5f);
        float m2 = fmaxf(tb * (1.0f / WELEMS), 1e-5f);
        g_wdq[0] = m1; g_wqs[0] = 1.0f / m1;
        g_wdq[1] = m2; g_wqs[1] = 1.0f / m2;
    }
}

__global__ void __launch_bounds__(256) wquant_kernel(const float* __restrict__ w1,
                                                     const float* __restrict__ w2) {
    const int which = blockIdx.y;
    const float4* w = reinterpret_cast<const float4*>(which ? w2 : w1);
    uint32_t* q = reinterpret_cast<uint32_t*>(which ? g_w2q : g_w1q);
    const float s = g_wqs[which];
    const int i = blockIdx.x * 256 + threadIdx.x;
    float4 v = w[i];
    q[i] = pack4(fminf(fmaxf(rintf(v.x * s), -1.f), 1.f),
                 fminf(fmaxf(rintf(v.y * s), -1.f), 1.f),
                 fminf(fmaxf(rintf(v.z * s), -1.f), 1.f),
                 fminf(fmaxf(rintf(v.w * s), -1.f), 1.f));
}

// ---------------- rmsnorm + per-token int8 quant ----------------
template <int D>
__global__ void __launch_bounds__(256) actq_kernel(const float* __restrict__ x,
                                                   int8_t* __restrict__ q,
                                                   float* __restrict__ dq) {
    constexpr int PER = D / 1024;
    const size_t rb = (size_t)blockIdx.x * D;
    const float4* xr = reinterpret_cast<const float4*>(x + rb);
    const int t = threadIdx.x;
    float4 v[PER];
    float ss = 0.f, am = 0.f;
    #pragma unroll
    for (int i = 0; i < PER; i++) {
        v[i] = xr[t + i * 256];
        ss += v[i].x * v[i].x; ss += v[i].y * v[i].y;
        ss += v[i].z * v[i].z; ss += v[i].w * v[i].w;
        am = fmaxf(am, fabsf(v[i].x)); am = fmaxf(am, fabsf(v[i].y));
        am = fmaxf(am, fabsf(v[i].z)); am = fmaxf(am, fabsf(v[i].w));
    }
    #pragma unroll
    for (int o = 16; o; o >>= 1) {
        ss += __shfl_xor_sync(~0u, ss, o);
        am = fmaxf(am, __shfl_xor_sync(~0u, am, o));
    }
    __shared__ float s_ss[8], s_am[8], s_r[2];
    if ((t & 31) == 0) { s_ss[t >> 5] = ss; s_am[t >> 5] = am; }
    __syncthreads();
    if (t == 0) {
        float tss = 0.f, tam = 0.f;
        #pragma unroll
        for (int i = 0; i < 8; i++) { tss += s_ss[i]; tam = fmaxf(tam, s_am[i]); }
        float ir = rsqrtf(tss * (1.0f / D) + 1e-5f);
        float sc = 127.0f / fmaxf(tam * ir, 1e-5f);
        s_r[0] = ir; s_r[1] = sc;
        dq[blockIdx.x] = 1.0f / sc;
    }
    __syncthreads();
    const float ir = s_r[0], sc = s_r[1];
    uint32_t* qr = reinterpret_cast<uint32_t*>(q + rb);
    #pragma unroll
    for (int i = 0; i < PER; i++) {
        qr[t + i * 256] = pack4(rintf((v[i].x * ir) * sc), rintf((v[i].y * ir) * sc),
                                rintf((v[i].z * ir) * sc), rintf((v[i].w * ir) * sc));
    }
}

// ---------------- int8 IMMA GEMM: BM=128, BN=128, BK=128(bytes), 4-stage cp.async ----------------
// C[m,n] = sum_k A[m,k]*B[n,k] (s32); out = C*adq[m]*wdq + bias[n] (+GELU)
#define ABYTES 16384u
#define STG    32768u
#define SMEM_DYN (4 * 32768 + 1024)

template <bool GELU>
__global__ void __launch_bounds__(256, 1)
bit_gemm(const int8_t* __restrict__ A, const int8_t* __restrict__ B,
         const float* __restrict__ adq, const float* __restrict__ wdq_p,
         const float* __restrict__ bias, float* __restrict__ out,
         int K, int Ntot) {
    extern __shared__ char dsm[];
    const uint32_t tb = (smem_u32(dsm) + 1023) & ~1023u;
    const int tid = threadIdx.x, lane = tid & 31, w = tid >> 5;
    const int wm = w & 3, wn = w >> 2;              // 4x2 warp grid; warp tile 32x64
    const int m0 = blockIdx.y * 128, n0 = blockIdx.x * 128, NK = K >> 7;

    auto stage_load = [&](int ks) {
        const uint32_t sb = tb + (uint32_t)(ks & 3) * STG;
        const size_t kk = (size_t)ks << 7;          // BK=128 int8 elements
        #pragma unroll
        for (int i = 0; i < 4; i++) {               // A: 128 rows x 128B
            int idx = i * 256 + tid, row = idx >> 3, c = idx & 7;
            cp16(sb + swz((uint32_t)idx * 16),
                 (const char*)A + (size_t)(m0 + row) * K + kk + c * 16);
        }
        #pragma unroll
        for (int i = 0; i < 4; i++) {               // B: 128 rows x 128B
            int idx = i * 256 + tid, row = idx >> 3, c = idx & 7;
            cp16(sb + ABYTES + swz((uint32_t)idx * 16),
                 (const char*)B + (size_t)(n0 + row) * K + kk + c * 16);
        }
    };

    int acc[2][8][4];
    #pragma unroll
    for (int i = 0; i < 2; i++)
        #pragma unroll
        for (int j = 0; j < 8; j++)
            #pragma unroll
            for (int u = 0; u < 4; u++) acc[i][j][u] = 0;

    #pragma unroll
    for (int p = 0; p < 3; p++) {                   // prologue: stages 0..2
        stage_load(p);
        asm volatile("cp.async.commit_group;" ::: "memory");
    }

    // per-lane fragment addresses (byte offsets; identical layout to bf16 case)
    const int a_row = wm * 32 + (lane & 15);        // + mt*16
    const int a_cb  = (lane >> 4) * 16;
    const int b_row = wn * 64 + (lane & 7) + ((lane >> 4) << 3);  // + g*16
    const int b_cb  = ((lane >> 3) & 1) * 16;

    for (int k = 0; k < NK; k++) {
        asm volatile("cp.async.wait_group 2;" ::: "memory");
        __syncthreads();
        const uint32_t sa = tb + (uint32_t)(k & 3) * STG;
        const uint32_t sbb = sa + ABYTES;
        #pragma unroll
        for (int ks = 0; ks < 4; ks++) {            // 4 x k32 int8 = BK 128
            uint32_t af[2][4], bf[4][4];
            #pragma unroll
            for (int mt = 0; mt < 2; mt++)
                ldsm4(af[mt], sa + swz((uint32_t)(a_row + mt * 16) * 128 + ks * 32 + a_cb));
            #pragma unroll
            for (int g = 0; g < 4; g++)
                ldsm4(bf[g], sbb + swz((uint32_t)(b_row + g * 16) * 128 + ks * 32 + b_cb));
            #pragma unroll
            for (int mt = 0; mt < 2; mt++)
                #pragma unroll
                for (int g = 0; g < 4; g++) {
                    mma_s8(acc[mt][2 * g],     af[mt], bf[g][0], bf[g][1]);
                    mma_s8(acc[mt][2 * g + 1], af[mt], bf[g][2], bf[g][3]);
                }
        }
        if (k + 3 < NK) stage_load(k + 3);
        asm volatile("cp.async.commit_group;" ::: "memory");
    }

    // epilogue (s32 sums < 2^19: exact in float)
    const float wdq = *wdq_p;
    #pragma unroll
    for (int mt = 0; mt < 2; mt++) {
        const int r0 = m0 + wm * 32 + mt * 16 + (lane >> 2);
        const float dq0 = adq[r0] * wdq, dq1 = adq[r0 + 8] * wdq;
        float* o0 = out + (size_t)r0 * Ntot;
        float* o1 = out + (size_t)(r0 + 8) * Ntot;
        #pragma unroll
        for (int nt = 0; nt < 8; nt++) {
            const int c = n0 + wn * 64 + nt * 8 + (lane & 3) * 2;
            const float2 bs = *reinterpret_cast<const float2*>(&bias[c]);
            float v0 = fmaf((float)acc[mt][nt][0], dq0, bs.x);
            float v1 = fmaf((float)acc[mt][nt][1], dq0, bs.y);
            float v2 = fmaf((float)acc[mt][nt][2], dq1, bs.x);
            float v3 = fmaf((float)acc[mt][nt][3], dq1, bs.y);
            if (GELU) {
                v0 = 0.5f * v0 * (1.0f + erff(v0 * 0.70710678118654752f));
                v1 = 0.5f * v1 * (1.0f + erff(v1 * 0.70710678118654752f));
                v2 = 0.5f * v2 * (1.0f + erff(v2 * 0.70710678118654752f));
                v3 = 0.5f * v3 * (1.0f + erff(v3 * 0.70710678118654752f));
            }
            *reinterpret_cast<float2*>(o0 + c) = make_float2(v0, v1);
            *reinterpret_cast<float2*>(o1 + c) = make_float2(v2, v3);
        }
    }
}

// ---------------- host ----------------
extern "C" void kernel_launch(void* const* d_in, const int* in_sizes, int n_in,
                              void* d_out, int out_size) {
    const float* x  = (const float*)d_in[0];
    const float* w1 = (const float*)d_in[1];
    const float* b1 = (const float*)d_in[2];
    const float* w2 = (const float*)d_in[3];
    const float* b2 = (const float*)d_in[4];

    void *p_xq, *p_hq, *p_w1q, *p_w2q, *p_h, *p_xdq, *p_hdq, *p_wdq;
    cudaGetSymbolAddress(&p_xq,  g_xq);
    cudaGetSymbolAddress(&p_hq,  g_hq);
    cudaGetSymbolAddress(&p_w1q, g_w1q);
    cudaGetSymbolAddress(&p_w2q, g_w2q);
    cudaGetSymbolAddress(&p_h,   g_h);
    cudaGetSymbolAddress(&p_xdq, g_xdq);
    cudaGetSymbolAddress(&p_hdq, g_hdq);
    cudaGetSymbolAddress(&p_wdq, g_wdq);

    cudaFuncSetAttribute(bit_gemm<true>,  cudaFuncAttributeMaxDynamicSharedMemorySize, SMEM_DYN);
    cudaFuncSetAttribute(bit_gemm<false>, cudaFuncAttributeMaxDynamicSharedMemorySize, SMEM_DYN);

    wabs_kernel<<<dim3(512, 2), 256>>>(w1, w2);
    wfin_kernel<<<1, 512>>>();
    wquant_kernel<<<dim3(4096, 2), 256>>>(w1, w2);
    actq_kernel<DIM><<<TOKENS, 256>>>(x, (int8_t*)p_xq, (float*)p_xdq);
    bit_gemm<true><<<dim3(INNER / 128, TOKENS / 128), 256, SMEM_DYN>>>(
        (const int8_t*)p_xq, (const int8_t*)p_w1q,
        (const float*)p_xdq, (const float*)p_wdq, b1, (float*)p_h, DIM, INNER);
    actq_kernel<INNER><<<TOKENS, 256>>>((const float*)p_h, (int8_t*)p_hq, (float*)p_hdq);
    bit_gemm<false><<<dim3(DIM / 128, TOKENS / 128), 256, SMEM_DYN>>>(
        (const int8_t*)p_hq, (const int8_t*)p_w2q,
        (const float*)p_hdq, (const float*)p_wdq + 1, b2, (float*)d_out, INNER, DIM);
}

// round 8
// speedup vs baseline: 1.6280x; 1.6280x over previous
#include <cuda_runtime.h>
#include <cuda_bf16.h>
#include <cstdint>
#include <cstddef>

#define TOKENS 16384
#define DIM    1024
#define INNER  4096
#define WELEMS 4194304  // 4096*1024

// ---------------- scratch (static device globals; no allocation) ----------------
__device__ __align__(1024) __nv_bfloat16 g_xq [(size_t)TOKENS * DIM];
__device__ __align__(1024) __nv_bfloat16 g_hq [(size_t)TOKENS * INNER];
__device__ __align__(1024) __nv_bfloat16 g_w1q[WELEMS];
__device__ __align__(1024) __nv_bfloat16 g_w2q[WELEMS];
__device__ __align__(1024) float         g_h  [(size_t)TOKENS * INNER];
__device__ float g_xdq[TOKENS];
__device__ float g_hdq[TOKENS];
__device__ float g_part[1024];
__device__ float g_wdq[2];   // dequant = clip(mean|w|,eps)
__device__ float g_wqs[2];   // 1/dequant

// ---------------- helpers ----------------
__device__ __forceinline__ uint32_t smem_u32(const void* p) {
    return (uint32_t)__cvta_generic_to_shared(p);
}
// SW128 swizzle on byte offsets (128B rows)
__device__ __forceinline__ uint32_t swz(uint32_t x) { return x ^ ((x >> 3) & 0x70); }

__device__ __forceinline__ void cp16(uint32_t s, const void* g) {
    asm volatile("cp.async.cg.shared.global [%0], [%1], 16;" :: "r"(s), "l"(g) : "memory");
}
__device__ __forceinline__ void ldsm4(uint32_t* r, uint32_t a) {
    asm volatile("ldmatrix.sync.aligned.m8n8.x4.shared.b16 {%0,%1,%2,%3}, [%4];"
                 : "=r"(r[0]), "=r"(r[1]), "=r"(r[2]), "=r"(r[3]) : "r"(a));
}
__device__ __forceinline__ void mma_bf16(float* c, const uint32_t* a, uint32_t b0, uint32_t b1) {
    asm volatile(
        "mma.sync.aligned.m16n8k16.row.col.f32.bf16.bf16.f32 "
        "{%0,%1,%2,%3}, {%4,%5,%6,%7}, {%8,%9}, {%0,%1,%2,%3};"
        : "+f"(c[0]), "+f"(c[1]), "+f"(c[2]), "+f"(c[3])
        : "r"(a[0]), "r"(a[1]), "r"(a[2]), "r"(a[3]), "r"(b0), "r"(b1));
}

// ---------------- weight quantization ----------------
__global__ void __launch_bounds__(256) wabs_kernel(const float* __restrict__ w1,
                                                   const float* __restrict__ w2) {
    const float* w = blockIdx.y ? w2 : w1;
    float s = 0.f;
    for (int i = blockIdx.x * 256 + threadIdx.x; i < WELEMS; i += 512 * 256)
        s += fabsf(w[i]);
    #pragma unroll
    for (int o = 16; o; o >>= 1) s += __shfl_xor_sync(~0u, s, o);
    __shared__ float sm[8];
    if ((threadIdx.x & 31) == 0) sm[threadIdx.x >> 5] = s;
    __syncthreads();
    if (threadIdx.x == 0) {
        float t = 0.f;
        #pragma unroll
        for (int i = 0; i < 8; i++) t += sm[i];
        g_part[blockIdx.y * 512 + blockIdx.x] = t;
    }
}

__global__ void __launch_bounds__(512) wfin_kernel() {
    int t = threadIdx.x;
    float a = g_part[t], b = g_part[512 + t];
    #pragma unroll
    for (int o = 16; o; o >>= 1) {
        a += __shfl_xor_sync(~0u, a, o);
        b += __shfl_xor_sync(~0u, b, o);
    }
    __shared__ float sa[16], sb[16];
    if ((t & 31) == 0) { sa[t >> 5] = a; sb[t >> 5] = b; }
    __syncthreads();
    if (t == 0) {
        float ta = 0.f, tb = 0.f;
        #pragma unroll
        for (int i = 0; i < 16; i++) { ta += sa[i]; tb += sb[i]; }
        float m1 = fmaxf(ta * (1.0f / WELEMS), 1e-5f);
        float m2 = fmaxf(tb * (1.0f / WELEMS), 1e-5f);
        g_wdq[0] = m1; g_wqs[0] = 1.0f / m1;
        g_wdq[1] = m2; g_wqs[1] = 1.0f / m2;
    }
}

__global__ void __launch_bounds__(256) wquant_kernel(const float* __restrict__ w1,
                                                     const float* __restrict__ w2) {
    const int which = blockIdx.y;
    const float4* w = reinterpret_cast<const float4*>(which ? w2 : w1);
    uint2* q = reinterpret_cast<uint2*>(which ? g_w2q : g_w1q);
    const float s = g_wqs[which];
    const int i = blockIdx.x * 256 + threadIdx.x;
    float4 v = w[i];
    float q0 = fminf(fmaxf(rintf(v.x * s), -1.f), 1.f);
    float q1 = fminf(fmaxf(rintf(v.y * s), -1.f), 1.f);
    float q2 = fminf(fmaxf(rintf(v.z * s), -1.f), 1.f);
    float q3 = fminf(fmaxf(rintf(v.w * s), -1.f), 1.f);
    uint32_t lo = ((uint32_t)__bfloat16_as_ushort(__float2bfloat16(q1)) << 16)
                |  (uint32_t)__bfloat16_as_ushort(__float2bfloat16(q0));
    uint32_t hi = ((uint32_t)__bfloat16_as_ushort(__float2bfloat16(q3)) << 16)
                |  (uint32_t)__bfloat16_as_ushort(__float2bfloat16(q2));
    q[i] = make_uint2(lo, hi);
}

// ---------------- rmsnorm + per-token int8 quant (stored as bf16 ints) ----------------
template <int D>
__global__ void __launch_bounds__(256) actq_kernel(const float* __restrict__ x,
                                                   __nv_bfloat16* __restrict__ q,
                                                   float* __restrict__ dq) {
    constexpr int PER = D / 1024;
    const size_t rb = (size_t)blockIdx.x * D;
    const float4* xr = reinterpret_cast<const float4*>(x + rb);
    const int t = threadIdx.x;
    float4 v[PER];
    float ss = 0.f, am = 0.f;
    #pragma unroll
    for (int i = 0; i < PER; i++) {
        v[i] = xr[t + i * 256];
        ss += v[i].x * v[i].x; ss += v[i].y * v[i].y;
        ss += v[i].z * v[i].z; ss += v[i].w * v[i].w;
        am = fmaxf(am, fabsf(v[i].x)); am = fmaxf(am, fabsf(v[i].y));
        am = fmaxf(am, fabsf(v[i].z)); am = fmaxf(am, fabsf(v[i].w));
    }
    #pragma unroll
    for (int o = 16; o; o >>= 1) {
        ss += __shfl_xor_sync(~0u, ss, o);
        am = fmaxf(am, __shfl_xor_sync(~0u, am, o));
    }
    __shared__ float s_ss[8], s_am[8], s_r[2];
    if ((t & 31) == 0) { s_ss[t >> 5] = ss; s_am[t >> 5] = am; }
    __syncthreads();
    if (t == 0) {
        float tss = 0.f, tam = 0.f;
        #pragma unroll
        for (int i = 0; i < 8; i++) { tss += s_ss[i]; tam = fmaxf(tam, s_am[i]); }
        float ir = rsqrtf(tss * (1.0f / D) + 1e-5f);
        float sc = 127.0f / fmaxf(tam * ir, 1e-5f);
        s_r[0] = ir; s_r[1] = sc;
        dq[blockIdx.x] = 1.0f / sc;
    }
    __syncthreads();
    const float ir = s_r[0], sc = s_r[1];
    uint2* qr = reinterpret_cast<uint2*>(q + rb);
    #pragma unroll
    for (int i = 0; i < PER; i++) {
        float a0 = fminf(fmaxf(rintf((v[i].x * ir) * sc), -128.f), 127.f);
        float a1 = fminf(fmaxf(rintf((v[i].y * ir) * sc), -128.f), 127.f);
        float a2 = fminf(fmaxf(rintf((v[i].z * ir) * sc), -128.f), 127.f);
        float a3 = fminf(fmaxf(rintf((v[i].w * ir) * sc), -128.f), 127.f);
        uint32_t lo = ((uint32_t)__bfloat16_as_ushort(__float2bfloat16(a1)) << 16)
                    |  (uint32_t)__bfloat16_as_ushort(__float2bfloat16(a0));
        uint32_t hi = ((uint32_t)__bfloat16_as_ushort(__float2bfloat16(a3)) << 16)
                    |  (uint32_t)__bfloat16_as_ushort(__float2bfloat16(a2));
        qr[t + i * 256] = make_uint2(lo, hi);
    }
}

// ---------------- mma.sync bf16 GEMM: BM=128, BN=256, BK=64, 4-stage cp.async ----------------
// 8 warps in 2x4 grid, warp tile 64x64 (mma:ldsm = 4.0)
// C[m,n] = sum_k A[m,k]*B[n,k]; out = C*adq[m]*wdq + bias[n] (+GELU)
#define ABYTES 16384u
#define BBYTES 32768u
#define STG    (ABYTES + BBYTES)
#define SMEM_DYN (4 * (ABYTES + BBYTES) + 1024)

template <bool GELU>
__global__ void __launch_bounds__(256, 1)
bit_gemm(const __nv_bfloat16* __restrict__ A, const __nv_bfloat16* __restrict__ B,
         const float* __restrict__ adq, const float* __restrict__ wdq_p,
         const float* __restrict__ bias, float* __restrict__ out,
         int K, int Ntot) {
    extern __shared__ char dsm[];
    const uint32_t tb = (smem_u32(dsm) + 1023) & ~1023u;
    const int tid = threadIdx.x, lane = tid & 31, w = tid >> 5;
    const int wm = w & 1, wn = w >> 1;              // 2x4 warp grid; warp tile 64x64
    const int m0 = blockIdx.y * 128, n0 = blockIdx.x * 256, NK = K >> 6;

    auto stage_load = [&](int ks) {
        const uint32_t sb = tb + (uint32_t)(ks & 3) * STG;
        const size_t kk = (size_t)ks << 6;
        #pragma unroll
        for (int i = 0; i < 4; i++) {               // A: 128 rows x 128B
            int idx = i * 256 + tid, row = idx >> 3, c = idx & 7;
            cp16(sb + swz((uint32_t)idx * 16),
                 (const char*)A + ((size_t)(m0 + row) * K + kk) * 2 + c * 16);
        }
        #pragma unroll
        for (int i = 0; i < 8; i++) {               // B: 256 rows x 128B
            int idx = i * 256 + tid, row = idx >> 3, c = idx & 7;
            cp16(sb + ABYTES + swz((uint32_t)idx * 16),
                 (const char*)B + ((size_t)(n0 + row) * K + kk) * 2 + c * 16);
        }
    };

    float acc[4][8][4];
    #pragma unroll
    for (int i = 0; i < 4; i++)
        #pragma unroll
        for (int j = 0; j < 8; j++)
            #pragma unroll
            for (int u = 0; u < 4; u++) acc[i][j][u] = 0.f;

    #pragma unroll
    for (int p = 0; p < 3; p++) {                   // prologue: stages 0..2
        stage_load(p);
        asm volatile("cp.async.commit_group;" ::: "memory");
    }

    // per-lane fragment addresses (pre-swizzle byte offsets built per k-step)
    const int a_row = wm * 64 + (lane & 15);        // + mt*16
    const int a_cb  = (lane >> 4) * 16;
    const int b_row = wn * 64 + (lane & 7) + ((lane >> 4) << 3);  // + g*16
    const int b_cb  = ((lane >> 3) & 1) * 16;

    for (int k = 0; k < NK; k++) {
        asm volatile("cp.async.wait_group 2;" ::: "memory");
        __syncthreads();
        const uint32_t sa = tb + (uint32_t)(k & 3) * STG;
        const uint32_t sbb = sa + ABYTES;
        #pragma unroll
        for (int ks = 0; ks < 4; ks++) {
            uint32_t af[4][4], bf[4][4];
            #pragma unroll
            for (int mt = 0; mt < 4; mt++)
                ldsm4(af[mt], sa + swz((uint32_t)(a_row + mt * 16) * 128 + ks * 32 + a_cb));
            #pragma unroll
            for (int g = 0; g < 4; g++)
                ldsm4(bf[g], sbb + swz((uint32_t)(b_row + g * 16) * 128 + ks * 32 + b_cb));
            #pragma unroll
            for (int mt = 0; mt < 4; mt++)
                #pragma unroll
                for (int g = 0; g < 4; g++) {
                    mma_bf16(acc[mt][2 * g],     af[mt], bf[g][0], bf[g][1]);
                    mma_bf16(acc[mt][2 * g + 1], af[mt], bf[g][2], bf[g][3]);
                }
        }
        if (k + 3 < NK) stage_load(k + 3);
        asm volatile("cp.async.commit_group;" ::: "memory");
    }

    // epilogue
    const float wdq = *wdq_p;
    #pragma unroll
    for (int mt = 0; mt < 4; mt++) {
        const int r0 = m0 + wm * 64 + mt * 16 + (lane >> 2);
        const float dq0 = adq[r0] * wdq, dq1 = adq[r0 + 8] * wdq;
        float* o0 = out + (size_t)r0 * Ntot;
        float* o1 = out + (size_t)(r0 + 8) * Ntot;
        #pragma unroll
        for (int nt = 0; nt < 8; nt++) {
            const int c = n0 + wn * 64 + nt * 8 + (lane & 3) * 2;
            const float2 bs = *reinterpret_cast<const float2*>(&bias[c]);
            float v0 = fmaf(acc[mt][nt][0], dq0, bs.x);
            float v1 = fmaf(acc[mt][nt][1], dq0, bs.y);
            float v2 = fmaf(acc[mt][nt][2], dq1, bs.x);
            float v3 = fmaf(acc[mt][nt][3], dq1, bs.y);
            if (GELU) {
                v0 = 0.5f * v0 * (1.0f + erff(v0 * 0.70710678118654752f));
                v1 = 0.5f * v1 * (1.0f + erff(v1 * 0.70710678118654752f));
                v2 = 0.5f * v2 * (1.0f + erff(v2 * 0.70710678118654752f));
                v3 = 0.5f * v3 * (1.0f + erff(v3 * 0.70710678118654752f));
            }
            *reinterpret_cast<float2*>(o0 + c) = make_float2(v0, v1);
            *reinterpret_cast<float2*>(o1 + c) = make_float2(v2, v3);
        }
    }
}

// ---------------- host ----------------
extern "C" void kernel_launch(void* const* d_in, const int* in_sizes, int n_in,
                              void* d_out, int out_size) {
    const float* x  = (const float*)d_in[0];
    const float* w1 = (const float*)d_in[1];
    const float* b1 = (const float*)d_in[2];
    const float* w2 = (const float*)d_in[3];
    const float* b2 = (const float*)d_in[4];

    void *p_xq, *p_hq, *p_w1q, *p_w2q, *p_h, *p_xdq, *p_hdq, *p_wdq;
    cudaGetSymbolAddress(&p_xq,  g_xq);
    cudaGetSymbolAddress(&p_hq,  g_hq);
    cudaGetSymbolAddress(&p_w1q, g_w1q);
    cudaGetSymbolAddress(&p_w2q, g_w2q);
    cudaGetSymbolAddress(&p_h,   g_h);
    cudaGetSymbolAddress(&p_xdq, g_xdq);
    cudaGetSymbolAddress(&p_hdq, g_hdq);
    cudaGetSymbolAddress(&p_wdq, g_wdq);

    cudaFuncSetAttribute(bit_gemm<true>,  cudaFuncAttributeMaxDynamicSharedMemorySize, SMEM_DYN);
    cudaFuncSetAttribute(bit_gemm<false>, cudaFuncAttributeMaxDynamicSharedMemorySize, SMEM_DYN);

    wabs_kernel<<<dim3(512, 2), 256>>>(w1, w2);
    wfin_kernel<<<1, 512>>>();
    wquant_kernel<<<dim3(4096, 2), 256>>>(w1, w2);
    actq_kernel<DIM><<<TOKENS, 256>>>(x, (__nv_bfloat16*)p_xq, (float*)p_xdq);
    bit_gemm<true><<<dim3(INNER / 256, TOKENS / 128), 256, SMEM_DYN>>>(
        (const __nv_bfloat16*)p_xq, (const __nv_bfloat16*)p_w1q,
        (const float*)p_xdq, (const float*)p_wdq, b1, (float*)p_h, DIM, INNER);
    actq_kernel<INNER><<<TOKENS, 256>>>((const float*)p_h, (__nv_bfloat16*)p_hq, (float*)p_hdq);
    bit_gemm<false><<<dim3(DIM / 256, TOKENS / 128), 256, SMEM_DYN>>>(
        (const __nv_bfloat16*)p_hq, (const __nv_bfloat16*)p_w2q,
        (const float*)p_hdq, (const float*)p_wdq + 1, b2, (float*)d_out, INNER, DIM);
}

// round 11
// speedup vs baseline: 2.5182x; 1.5468x over previous
#include <cuda_runtime.h>
#include <cuda_bf16.h>
#include <cstdint>
#include <cstddef>

#define TOKENS 16384
#define DIM    1024
#define INNER  4096
#define WELEMS 4194304  // 4096*1024

// ---------------- scratch (static device globals; no allocation) ----------------
__device__ __align__(1024) __nv_bfloat16 g_xq [(size_t)TOKENS * DIM];
__device__ __align__(1024) __nv_bfloat16 g_hq [(size_t)TOKENS * INNER];
__device__ __align__(1024) __nv_bfloat16 g_w1q[WELEMS];
__device__ __align__(1024) __nv_bfloat16 g_w2q[WELEMS];
__device__ __align__(1024) float         g_h  [(size_t)TOKENS * INNER];  // fp32 (bf16 broke accuracy)
__device__ float g_xdq[TOKENS];
__device__ float g_hdq[TOKENS];
__device__ float g_part[1024];
__device__ float g_wdq[2];   // dequant = clip(mean|w|,eps)
__device__ float g_wqs[2];   // 1/dequant

// ---------------- helpers ----------------
__device__ __forceinline__ uint32_t smem_u32(const void* p) {
    return (uint32_t)__cvta_generic_to_shared(p);
}
// SW128 swizzle on byte offsets (128B rows)
__device__ __forceinline__ uint32_t swz(uint32_t x) { return x ^ ((x >> 3) & 0x70); }

__device__ __forceinline__ void cp16(uint32_t s, const void* g) {
    asm volatile("cp.async.cg.shared.global [%0], [%1], 16;" :: "r"(s), "l"(g) : "memory");
}
__device__ __forceinline__ void ldsm4(uint32_t* r, uint32_t a) {
    asm volatile("ldmatrix.sync.aligned.m8n8.x4.shared.b16 {%0,%1,%2,%3}, [%4];"
                 : "=r"(r[0]), "=r"(r[1]), "=r"(r[2]), "=r"(r[3]) : "r"(a));
}
__device__ __forceinline__ void mma_bf16(float* c, const uint32_t* a, uint32_t b0, uint32_t b1) {
    asm volatile(
        "mma.sync.aligned.m16n8k16.row.col.f32.bf16.bf16.f32 "
        "{%0,%1,%2,%3}, {%4,%5,%6,%7}, {%8,%9}, {%0,%1,%2,%3};"
        : "+f"(c[0]), "+f"(c[1]), "+f"(c[2]), "+f"(c[3])
        : "r"(a[0]), "r"(a[1]), "r"(a[2]), "r"(a[3]), "r"(b0), "r"(b1));
}
__device__ __forceinline__ uint32_t f2bf2(float a, float b) {
    return ((uint32_t)__bfloat16_as_ushort(__float2bfloat16(b)) << 16)
         |  (uint32_t)__bfloat16_as_ushort(__float2bfloat16(a));
}

// ---------------- weight quantization ----------------
__global__ void __launch_bounds__(256) wabs_kernel(const float* __restrict__ w1,
                                                   const float* __restrict__ w2) {
    const float* w = blockIdx.y ? w2 : w1;
    float s = 0.f;
    for (int i = blockIdx.x * 256 + threadIdx.x; i < WELEMS; i += 512 * 256)
        s += fabsf(w[i]);
    #pragma unroll
    for (int o = 16; o; o >>= 1) s += __shfl_xor_sync(~0u, s, o);
    __shared__ float sm[8];
    if ((threadIdx.x & 31) == 0) sm[threadIdx.x >> 5] = s;
    __syncthreads();
    if (threadIdx.x == 0) {
        float t = 0.f;
        #pragma unroll
        for (int i = 0; i < 8; i++) t += sm[i];
        g_part[blockIdx.y * 512 + blockIdx.x] = t;
    }
}

__global__ void __launch_bounds__(512) wfin_kernel() {
    int t = threadIdx.x;
    float a = g_part[t], b = g_part[512 + t];
    #pragma unroll
    for (int o = 16; o; o >>= 1) {
        a += __shfl_xor_sync(~0u, a, o);
        b += __shfl_xor_sync(~0u, b, o);
    }
    __shared__ float sa[16], sb[16];
    if ((t & 31) == 0) { sa[t >> 5] = a; sb[t >> 5] = b; }
    __syncthreads();
    if (t == 0) {
        float ta = 0.f, tb = 0.f;
        #pragma unroll
        for (int i = 0; i < 16; i++) { ta += sa[i]; tb += sb[i]; }
        float m1 = fmaxf(ta * (1.0f / WELEMS), 1e-5f);
        float m2 = fmaxf(tb * (1.0f / WELEMS), 1e-5f);
        g_wdq[0] = m1; g_wqs[0] = 1.0f / m1;
        g_wdq[1] = m2; g_wqs[1] = 1.0f / m2;
    }
}

__global__ void __launch_bounds__(256) wquant_kernel(const float* __restrict__ w1,
                                                     const float* __restrict__ w2) {
    const int which = blockIdx.y;
    const float4* w = reinterpret_cast<const float4*>(which ? w2 : w1);
    uint2* q = reinterpret_cast<uint2*>(which ? g_w2q : g_w1q);
    const float s = g_wqs[which];
    const int i = blockIdx.x * 256 + threadIdx.x;
    float4 v = w[i];
    uint32_t lo = f2bf2(fminf(fmaxf(rintf(v.x * s), -1.f), 1.f),
                        fminf(fmaxf(rintf(v.y * s), -1.f), 1.f));
    uint32_t hi = f2bf2(fminf(fmaxf(rintf(v.z * s), -1.f), 1.f),
                        fminf(fmaxf(rintf(v.w * s), -1.f), 1.f));
    q[i] = make_uint2(lo, hi);
}

// ---------------- rmsnorm + per-token int8 quant (fp32 in, bf16-int out) ----------------
template <int D>
__global__ void __launch_bounds__(256) actq_kernel(const float* __restrict__ x,
                                                   __nv_bfloat16* __restrict__ q,
                                                   float* __restrict__ dq) {
    constexpr int PER = D / 1024;
    const size_t rb = (size_t)blockIdx.x * D;
    const float4* xr = reinterpret_cast<const float4*>(x + rb);
    const int t = threadIdx.x;
    float4 v[PER];
    float ss = 0.f, am = 0.f;
    #pragma unroll
    for (int i = 0; i < PER; i++) {
        v[i] = xr[t + i * 256];
        ss += v[i].x * v[i].x; ss += v[i].y * v[i].y;
        ss += v[i].z * v[i].z; ss += v[i].w * v[i].w;
        am = fmaxf(am, fabsf(v[i].x)); am = fmaxf(am, fabsf(v[i].y));
        am = fmaxf(am, fabsf(v[i].z)); am = fmaxf(am, fabsf(v[i].w));
    }
    #pragma unroll
    for (int o = 16; o; o >>= 1) {
        ss += __shfl_xor_sync(~0u, ss, o);
        am = fmaxf(am, __shfl_xor_sync(~0u, am, o));
    }
    __shared__ float s_ss[8], s_am[8], s_r[2];
    if ((t & 31) == 0) { s_ss[t >> 5] = ss; s_am[t >> 5] = am; }
    __syncthreads();
    if (t == 0) {
        float tss = 0.f, tam = 0.f;
        #pragma unroll
        for (int i = 0; i < 8; i++) { tss += s_ss[i]; tam = fmaxf(tam, s_am[i]); }
        float ir = rsqrtf(tss * (1.0f / D) + 1e-5f);
        float sc = 127.0f / fmaxf(tam * ir, 1e-5f);
        s_r[0] = ir; s_r[1] = sc;
        dq[blockIdx.x] = 1.0f / sc;
    }
    __syncthreads();
    const float ir = s_r[0], sc = s_r[1];
    uint2* qr = reinterpret_cast<uint2*>(q + rb);
    #pragma unroll
    for (int i = 0; i < PER; i++) {
        float a0 = fminf(fmaxf(rintf((v[i].x * ir) * sc), -128.f), 127.f);
        float a1 = fminf(fmaxf(rintf((v[i].y * ir) * sc), -128.f), 127.f);
        float a2 = fminf(fmaxf(rintf((v[i].z * ir) * sc), -128.f), 127.f);
        float a3 = fminf(fmaxf(rintf((v[i].w * ir) * sc), -128.f), 127.f);
        qr[t + i * 256] = make_uint2(f2bf2(a0, a1), f2bf2(a2, a3));
    }
}

// ---------------- mma.sync bf16 GEMM: BM=128, BN=128, BK=64, 3-stage, occ=2 ----------------
// 8 warps in 4x2 grid, warp tile 32x64 (R5 core)
// C[m,n] = sum_k A[m,k]*B[n,k]; out = C*adq[m]*wdq + bias[n] (+GELU)
#define ABYTES 16384u
#define STG    32768u
#define SMEM_DYN (3 * 32768 + 1024)

template <bool GELU>
__global__ void __launch_bounds__(256, 2)
bit_gemm(const __nv_bfloat16* __restrict__ A, const __nv_bfloat16* __restrict__ B,
         const float* __restrict__ adq, const float* __restrict__ wdq_p,
         const float* __restrict__ bias, float* __restrict__ out,
         int K, int Ntot) {
    extern __shared__ char dsm[];
    const uint32_t tb = (smem_u32(dsm) + 1023) & ~1023u;
    const int tid = threadIdx.x, lane = tid & 31, w = tid >> 5;
    const int wm = w & 3, wn = w >> 2;              // 4x2 warp grid; warp tile 32x64
    const int m0 = blockIdx.y * 128, n0 = blockIdx.x * 128, NK = K >> 6;

    auto stage_load = [&](int ks) {
        const uint32_t sb = tb + (uint32_t)(ks % 3) * STG;
        const size_t kk = (size_t)ks << 6;
        #pragma unroll
        for (int i = 0; i < 4; i++) {               // A: 128 rows x 128B
            int idx = i * 256 + tid, row = idx >> 3, c = idx & 7;
            cp16(sb + swz((uint32_t)idx * 16),
                 (const char*)A + ((size_t)(m0 + row) * K + kk) * 2 + c * 16);
        }
        #pragma unroll
        for (int i = 0; i < 4; i++) {               // B: 128 rows x 128B
            int idx = i * 256 + tid, row = idx >> 3, c = idx & 7;
            cp16(sb + ABYTES + swz((uint32_t)idx * 16),
                 (const char*)B + ((size_t)(n0 + row) * K + kk) * 2 + c * 16);
        }
    };

    float acc[2][8][4];
    #pragma unroll
    for (int i = 0; i < 2; i++)
        #pragma unroll
        for (int j = 0; j < 8; j++)
            #pragma unroll
            for (int u = 0; u < 4; u++) acc[i][j][u] = 0.f;

    #pragma unroll
    for (int p = 0; p < 2; p++) {                   // prologue: stages 0,1
        stage_load(p);
        asm volatile("cp.async.commit_group;" ::: "memory");
    }

    const int a_row = wm * 32 + (lane & 15);        // + mt*16
    const int a_cb  = (lane >> 4) * 16;
    const int b_row = wn * 64 + (lane & 7) + ((lane >> 4) << 3);  // + g*16
    const int b_cb  = ((lane >> 3) & 1) * 16;

    for (int k = 0; k < NK; k++) {
        asm volatile("cp.async.wait_group 1;" ::: "memory");
        __syncthreads();
        const uint32_t sa = tb + (uint32_t)(k % 3) * STG;
        const uint32_t sbb = sa + ABYTES;
        #pragma unroll
        for (int ks = 0; ks < 4; ks++) {
            uint32_t af[2][4], bf[4][4];
            #pragma unroll
            for (int mt = 0; mt < 2; mt++)
                ldsm4(af[mt], sa + swz((uint32_t)(a_row + mt * 16) * 128 + ks * 32 + a_cb));
            #pragma unroll
            for (int g = 0; g < 4; g++)
                ldsm4(bf[g], sbb + swz((uint32_t)(b_row + g * 16) * 128 + ks * 32 + b_cb));
            #pragma unroll
            for (int mt = 0; mt < 2; mt++)
                #pragma unroll
                for (int g = 0; g < 4; g++) {
                    mma_bf16(acc[mt][2 * g],     af[mt], bf[g][0], bf[g][1]);
                    mma_bf16(acc[mt][2 * g + 1], af[mt], bf[g][2], bf[g][3]);
                }
        }
        if (k + 2 < NK) stage_load(k + 2);
        asm volatile("cp.async.commit_group;" ::: "memory");
    }

    // epilogue
    const float wdq = *wdq_p;
    #pragma unroll
    for (int mt = 0; mt < 2; mt++) {
        const int r0 = m0 + wm * 32 + mt * 16 + (lane >> 2);
        const float dq0 = adq[r0] * wdq, dq1 = adq[r0 + 8] * wdq;
        float* o0 = out + (size_t)r0 * Ntot;
        float* o1 = out + (size_t)(r0 + 8) * Ntot;
        #pragma unroll
        for (int nt = 0; nt < 8; nt++) {
            const int c = n0 + wn * 64 + nt * 8 + (lane & 3) * 2;
            const float2 bs = *reinterpret_cast<const float2*>(&bias[c]);
            float v0 = fmaf(acc[mt][nt][0], dq0, bs.x);
            float v1 = fmaf(acc[mt][nt][1], dq0, bs.y);
            float v2 = fmaf(acc[mt][nt][2], dq1, bs.x);
            float v3 = fmaf(acc[mt][nt][3], dq1, bs.y);
            if (GELU) {
                v0 = 0.5f * v0 * (1.0f + erff(v0 * 0.70710678118654752f));
                v1 = 0.5f * v1 * (1.0f + erff(v1 * 0.70710678118654752f));
                v2 = 0.5f * v2 * (1.0f + erff(v2 * 0.70710678118654752f));
                v3 = 0.5f * v3 * (1.0f + erff(v3 * 0.70710678118654752f));
            }
            *reinterpret_cast<float2*>(o0 + c) = make_float2(v0, v1);
            *reinterpret_cast<float2*>(o1 + c) = make_float2(v2, v3);
        }
    }
}

// ---------------- host ----------------
extern "C" void kernel_launch(void* const* d_in, const int* in_sizes, int n_in,
                              void* d_out, int out_size) {
    const float* x  = (const float*)d_in[0];
    const float* w1 = (const float*)d_in[1];
    const float* b1 = (const float*)d_in[2];
    const float* w2 = (const float*)d_in[3];
    const float* b2 = (const float*)d_in[4];

    void *p_xq, *p_hq, *p_w1q, *p_w2q, *p_h, *p_xdq, *p_hdq, *p_wdq;
    cudaGetSymbolAddress(&p_xq,  g_xq);
    cudaGetSymbolAddress(&p_hq,  g_hq);
    cudaGetSymbolAddress(&p_w1q, g_w1q);
    cudaGetSymbolAddress(&p_w2q, g_w2q);
    cudaGetSymbolAddress(&p_h,   g_h);
    cudaGetSymbolAddress(&p_xdq, g_xdq);
    cudaGetSymbolAddress(&p_hdq, g_hdq);
    cudaGetSymbolAddress(&p_wdq, g_wdq);

    cudaFuncSetAttribute(bit_gemm<true>,  cudaFuncAttributeMaxDynamicSharedMemorySize, SMEM_DYN);
    cudaFuncSetAttribute(bit_gemm<false>, cudaFuncAttributeMaxDynamicSharedMemorySize, SMEM_DYN);

    wabs_kernel<<<dim3(512, 2), 256>>>(w1, w2);
    wfin_kernel<<<1, 512>>>();
    wquant_kernel<<<dim3(4096, 2), 256>>>(w1, w2);
    actq_kernel<DIM><<<TOKENS, 256>>>(x, (__nv_bfloat16*)p_xq, (float*)p_xdq);
    bit_gemm<true><<<dim3(INNER / 128, TOKENS / 128), 256, SMEM_DYN>>>(
        (const __nv_bfloat16*)p_xq, (const __nv_bfloat16*)p_w1q,
        (const float*)p_xdq, (const float*)p_wdq, b1, (float*)p_h, DIM, INNER);
    actq_kernel<INNER><<<TOKENS, 256>>>((const float*)p_h, (__nv_bfloat16*)p_hq, (float*)p_hdq);
    bit_gemm<false><<<dim3(DIM / 128, TOKENS / 128), 256, SMEM_DYN>>>(
        (const __nv_bfloat16*)p_hq, (const __nv_bfloat16*)p_w2q,
        (const float*)p_hdq, (const float*)p_wdq + 1, b2, (float*)d_out, INNER, DIM);
}